// round 3
// baseline (speedup 1.0000x reference)
#include <cuda_runtime.h>
#include <cstdint>
#include <cstddef>

#define TT 2048
#define BB 32
#define HH 256
#define NCTA 128
#define NCELL (TT * 2)

// ---------------- global scratch (allocation-free: __device__ globals) ----------
__device__ float g_gi[(size_t)TT * BB * 3 * HH];   // x @ w_ih^T + b_ih  [T][B][768]
__device__ float g_h[2][HH * BB];                  // COLUMN-major: [col][b], double buffered
__device__ unsigned g_flags[NCTA];                 // monotonic per-CTA publish counters

// ---------------- acquire/release helpers --------------------------------------
__device__ __forceinline__ unsigned ld_acq(const unsigned* p) {
  unsigned v;
  asm volatile("ld.acquire.gpu.global.u32 %0, [%1];" : "=r"(v) : "l"(p) : "memory");
  return v;
}
__device__ __forceinline__ void st_rel(unsigned* p, unsigned v) {
  asm volatile("st.release.gpu.global.u32 [%0], %1;" :: "l"(p), "r"(v) : "memory");
}

// ---------------- gi precompute: g_gi[t][b][g] = x_t[b]·w_ih[g] + b_ih[g] -------
__global__ __launch_bounds__(256) void gi_kernel(
    const float* __restrict__ x, const float* __restrict__ w_ih,
    const float* __restrict__ b_ih) {
  __shared__ float xs[32 * 260];
  __shared__ float ws[128 * 20];
  const int t   = blockIdx.x;
  const int gc0 = blockIdx.y * 128;
  const int tid = threadIdx.x;

  for (int i = tid; i < 2048; i += 256) {
    int b = i >> 6;
    int c4 = (i & 63) << 2;
    float4 v = *(const float4*)(x + ((size_t)b * TT + t) * HH + c4);
    *(float4*)(xs + b * 260 + c4) = v;
  }

  const int bq = tid >> 5;
  const int gq = tid & 31;

  float acc[4][4];
#pragma unroll
  for (int i = 0; i < 4; i++)
#pragma unroll
    for (int j = 0; j < 4; j++) acc[i][j] = 0.f;

  for (int kt = 0; kt < 16; ++kt) {
    const int k0 = kt * 16;
    __syncthreads();
    for (int i = tid; i < 512; i += 256) {
      int r = i >> 2;
      int c4 = (i & 3) << 2;
      *(float4*)(ws + r * 20 + c4) =
          *(const float4*)(w_ih + (size_t)(gc0 + r) * HH + k0 + c4);
    }
    __syncthreads();
#pragma unroll
    for (int q = 0; q < 4; ++q) {
      const int kk = q << 2;
      float4 wv[4];
#pragma unroll
      for (int j = 0; j < 4; j++)
        wv[j] = *(const float4*)(ws + (gq + 32 * j) * 20 + kk);
#pragma unroll
      for (int i = 0; i < 4; i++) {
        float4 xv = *(const float4*)(xs + (bq * 4 + i) * 260 + k0 + kk);
#pragma unroll
        for (int j = 0; j < 4; j++) {
          acc[i][j] += xv.x * wv[j].x + xv.y * wv[j].y +
                       xv.z * wv[j].z + xv.w * wv[j].w;
        }
      }
    }
  }
#pragma unroll
  for (int j = 0; j < 4; j++) {
    int g = gc0 + gq + 32 * j;
    float bias = b_ih[g];
#pragma unroll
    for (int i = 0; i < 4; i++) {
      int b = bq * 4 + i;
      g_gi[((size_t)t * BB + b) * 768 + g] = acc[i][j] + bias;
    }
  }
}

// ---------------- persistent recurrent scan with flag-based sync ----------------
// 128 CTAs, CTA c owns h columns {2c, 2c+1} -> 6 gate rows of w_hh in SMEM.
// Per cell: load h^T into SMEM, compute partial gh (K split 8-way over warps),
// reduce, gates; warps 0-1 do the epilogue+publish while warps 2-5 already poll
// the other 127 CTAs' flags for the next cell.
__global__ __launch_bounds__(256) void scan_kernel(
    const float* __restrict__ hidden, const float* __restrict__ w_hh,
    const float* __restrict__ b_hh, float* __restrict__ out) {
  __shared__ float hT[HH * BB];        // h transposed: hT[k*32 + b]  (32 KB)
  __shared__ float w_s[6 * 260];       // rows r = g*2+jj over K=256
  __shared__ float part[8 * 32 * 2 * 3];
  __shared__ float bhh_s[8];
  __shared__ unsigned s_base;

  const int tid = threadIdx.x;
  const int c   = blockIdx.x;

  if (tid == 0) s_base = __ldcg(&g_flags[c]);  // all flags equal at launch

  // persistent w_hh slice
  for (int i = tid; i < 6 * 64; i += 256) {
    int r  = i >> 6;               // 0..5 = g*2+jj
    int c4 = (i & 63) << 2;
    int g  = r >> 1, jj = r & 1;
    *(float4*)(w_s + r * 260 + c4) =
        *(const float4*)(w_hh + (size_t)(g * HH + c * 2 + jj) * HH + c4);
  }
  if (tid < 6) {
    int g = tid >> 1, jj = tid & 1;
    bhh_s[tid] = b_hh[g * HH + c * 2 + jj];
  }
  __syncthreads();

  const unsigned base = s_base;
  const int warp = tid >> 5;
  const int lane = tid & 31;
  const int jj   = lane & 1;
  const int b0   = (lane >> 1) << 1;   // 2 consecutive batches
  const int k0   = warp << 5;          // 8-way K split

  for (int cell = 0; cell < NCELL; ++cell) {
    // ---- load h^T into SMEM ----
    if (cell == 0) {
      for (int i = tid; i < HH * BB; i += 256)
        hT[(i & 255) * 32 + (i >> 8)] = hidden[i];   // transpose [b][col]->[col][b]
    } else {
      const float4* src = (const float4*)(g_h[cell & 1]);
      float4* dst = (float4*)hT;
#pragma unroll
      for (int q = 0; q < 8; ++q)
        dst[tid + q * 256] = __ldcg(src + tid + q * 256);
    }
    // prefetch gi for epilogue threads (latency hidden behind compute)
    float gir = 0.f, giz = 0.f, gin = 0.f;
    if (tid < 64) {
      int b = tid >> 1, j2 = tid & 1;
      const float* gp = g_gi + (size_t)(cell >> 1) * BB * 768 + b * 768 + c * 2 + j2;
      gir = gp[0];
      giz = gp[256];
      gin = gp[512];
    }
    __syncthreads();

    // ---- partial gh: acc[2 batches][3 gates] over K range [k0, k0+32) ----
    float acc[2][3];
#pragma unroll
    for (int bi = 0; bi < 2; ++bi)
#pragma unroll
      for (int g = 0; g < 3; ++g) acc[bi][g] = 0.f;

    const float* wr = w_s + jj * 260;
    const float* wz = w_s + (2 + jj) * 260;
    const float* wn = w_s + (4 + jj) * 260;
#pragma unroll
    for (int kq = 0; kq < 8; ++kq) {
      const int k = k0 + (kq << 2);
      const float4 wrv = *(const float4*)(wr + k);
      const float4 wzv = *(const float4*)(wz + k);
      const float4 wnv = *(const float4*)(wn + k);
#pragma unroll
      for (int u = 0; u < 4; ++u) {
        const float2 hv = *(const float2*)(hT + (k + u) * 32 + b0);
        const float wrx = (&wrv.x)[u];
        const float wzx = (&wzv.x)[u];
        const float wnx = (&wnv.x)[u];
        acc[0][0] += hv.x * wrx;  acc[1][0] += hv.y * wrx;
        acc[0][1] += hv.x * wzx;  acc[1][1] += hv.y * wzx;
        acc[0][2] += hv.x * wnx;  acc[1][2] += hv.y * wnx;
      }
    }
    {
      float* p0 = part + ((warp * 32 + b0) * 2 + jj) * 3;
      p0[0] = acc[0][0]; p0[1] = acc[0][1]; p0[2] = acc[0][2];
      float* p1 = part + ((warp * 32 + b0 + 1) * 2 + jj) * 3;
      p1[0] = acc[1][0]; p1[1] = acc[1][1]; p1[2] = acc[1][2];
    }
    __syncthreads();

    // ---- epilogue (warps 0-1) overlapped with next-cell polling (warps 2-5) ----
    if (tid < 64) {
      const int b = tid >> 1, j2 = tid & 1;
      float sr = bhh_s[j2], sz = bhh_s[2 + j2], sn = bhh_s[4 + j2];
#pragma unroll
      for (int kh = 0; kh < 8; ++kh) {
        const float* p = part + ((kh * 32 + b) * 2 + j2) * 3;
        sr += p[0];
        sz += p[1];
        sn += p[2];
      }
      const float r = 1.f / (1.f + expf(-(gir + sr)));
      const float z = 1.f / (1.f + expf(-(giz + sz)));
      const float n = tanhf(gin + r * sn);
      const float hold = hT[(c * 2 + j2) * 32 + b];
      const float hn = (1.f - z) * n + z * hold;
      g_h[(cell + 1) & 1][(c * 2 + j2) * 32 + b] = hn;
      if (cell & 1)
        out[((size_t)(cell >> 1) * BB + b) * HH + c * 2 + j2] = hn;
      asm volatile("bar.sync 1, 64;" ::: "memory");   // warps 0-1 only
      if (tid == 0) {
        __threadfence();
        st_rel(&g_flags[c], base + cell + 1);
      }
    } else if (tid < 192 && cell + 1 < NCELL) {
      // poll one producer flag each: wait for ALL CTAs to publish this cell
      const unsigned tgt = base + cell + 1;
      const unsigned* fp = &g_flags[tid - 64];
      while ((int)(ld_acq(fp) - tgt) < 0) {}
    }
    __syncthreads();
  }
}

// ---------------- launch --------------------------------------------------------
extern "C" void kernel_launch(void* const* d_in, const int* in_sizes, int n_in,
                              void* d_out, int out_size) {
  const float *input = 0, *hidden = 0, *w_ih = 0, *w_hh = 0, *b_ih = 0, *b_hh = 0;
  for (int i = 0; i < n_in; ++i) {
    long s = in_sizes[i];
    if (s == (long)BB * TT * HH) {
      input = (const float*)d_in[i];
    } else if (s == BB * HH && !hidden) {
      hidden = (const float*)d_in[i];
    } else if (s == 3 * HH * HH) {
      if (!w_ih) w_ih = (const float*)d_in[i]; else w_hh = (const float*)d_in[i];
    } else if (s == 3 * HH) {
      if (!b_ih) b_ih = (const float*)d_in[i]; else b_hh = (const float*)d_in[i];
    }
  }
  gi_kernel<<<dim3(TT, 6), 256>>>(input, w_ih, b_ih);
  scan_kernel<<<NCTA, 256>>>(hidden, w_hh, b_hh, (float*)d_out);
}

// round 4
// speedup vs baseline: 2.3765x; 2.3765x over previous
#include <cuda_runtime.h>
#include <cstdint>
#include <cstddef>

#define TT 2048
#define BB 32
#define HH 256
#define NCTA 64
#define NCELL (TT * 2)

// ---------------- global scratch (allocation-free) ------------------------------
__device__ float g_gi[(size_t)TT * BB * 3 * HH];   // x @ w_ih^T + b_ih  [T][B][768]
__device__ float g_h[2][HH * BB];                  // col-major [col][b], double buffered
__device__ unsigned g_ctr;                         // arrival counter (zeroed per launch)

// ---------------- sync primitives ----------------------------------------------
__device__ __forceinline__ unsigned ld_acq(const unsigned* p) {
  unsigned v;
  asm volatile("ld.acquire.gpu.global.u32 %0, [%1];" : "=r"(v) : "l"(p) : "memory");
  return v;
}
__device__ __forceinline__ void red_add(unsigned* p, unsigned v) {
  asm volatile("red.relaxed.gpu.global.add.u32 [%0], %1;" :: "l"(p), "r"(v) : "memory");
}

// ---------------- packed f32x2 helpers ------------------------------------------
__device__ __forceinline__ uint64_t pack2(float a, float b) {
  uint64_t r;
  asm("mov.b64 %0, {%1, %2};" : "=l"(r) : "f"(a), "f"(b));
  return r;
}
__device__ __forceinline__ void unpack2(float& a, float& b, uint64_t v) {
  asm("mov.b64 {%0, %1}, %2;" : "=f"(a), "=f"(b) : "l"(v));
}
__device__ __forceinline__ void fma2(uint64_t& d, uint64_t a, uint64_t b) {
  asm("fma.rn.f32x2 %0, %1, %2, %0;" : "+l"(d) : "l"(a), "l"(b));
}

// ---------------- per-launch counter reset --------------------------------------
__global__ void zero_ctr_kernel() { g_ctr = 0u; }

// ---------------- gi precompute: g_gi[t][b][g] = x_t[b]·w_ih[g] + b_ih[g] -------
__global__ __launch_bounds__(256) void gi_kernel(
    const float* __restrict__ x, const float* __restrict__ w_ih,
    const float* __restrict__ b_ih) {
  __shared__ float xs[32 * 260];
  __shared__ float ws[128 * 20];
  const int t   = blockIdx.x;
  const int gc0 = blockIdx.y * 128;
  const int tid = threadIdx.x;

  for (int i = tid; i < 2048; i += 256) {
    int b = i >> 6;
    int c4 = (i & 63) << 2;
    float4 v = *(const float4*)(x + ((size_t)b * TT + t) * HH + c4);
    *(float4*)(xs + b * 260 + c4) = v;
  }

  const int bq = tid >> 5;
  const int gq = tid & 31;

  float acc[4][4];
#pragma unroll
  for (int i = 0; i < 4; i++)
#pragma unroll
    for (int j = 0; j < 4; j++) acc[i][j] = 0.f;

  for (int kt = 0; kt < 16; ++kt) {
    const int k0 = kt * 16;
    __syncthreads();
    for (int i = tid; i < 512; i += 256) {
      int r = i >> 2;
      int c4 = (i & 3) << 2;
      *(float4*)(ws + r * 20 + c4) =
          *(const float4*)(w_ih + (size_t)(gc0 + r) * HH + k0 + c4);
    }
    __syncthreads();
#pragma unroll
    for (int q = 0; q < 4; ++q) {
      const int kk = q << 2;
      float4 wv[4];
#pragma unroll
      for (int j = 0; j < 4; j++)
        wv[j] = *(const float4*)(ws + (gq + 32 * j) * 20 + kk);
#pragma unroll
      for (int i = 0; i < 4; i++) {
        float4 xv = *(const float4*)(xs + (bq * 4 + i) * 260 + k0 + kk);
#pragma unroll
        for (int j = 0; j < 4; j++) {
          acc[i][j] += xv.x * wv[j].x + xv.y * wv[j].y +
                       xv.z * wv[j].z + xv.w * wv[j].w;
        }
      }
    }
  }
#pragma unroll
  for (int j = 0; j < 4; j++) {
    int g = gc0 + gq + 32 * j;
    float bias = b_ih[g];
#pragma unroll
    for (int i = 0; i < 4; i++) {
      int b = bq * 4 + i;
      g_gi[((size_t)t * BB + b) * 768 + g] = acc[i][j] + bias;
    }
  }
}

// ---------------- persistent recurrent scan -------------------------------------
// 64 CTAs; CTA c owns h columns c*4..c*4+3 (12 gate rows, held in REGISTERS).
// Thread (kh, jj, bt): kh = K-slice of 16, jj = local col, bt = batch octet.
// Sync: one monotonic counter; red.relaxed arrivals, one poller thread per CTA,
// polling overlapped with the epilogue of the current cell.
__global__ __launch_bounds__(256, 1) void scan_kernel(
    const float* __restrict__ hidden, const float* __restrict__ w_hh,
    const float* __restrict__ b_hh, float* __restrict__ out) {
  extern __shared__ float sm[];
  float* hT   = sm;                  // [k][b] : 256*32 floats (32 KB)
  float* part = sm + HH * BB;        // 256 threads * 25 floats (25 KB)
  float* bhh  = part + 256 * 25;     // 12 floats, bhh[g*4+jj]

  const int tid = threadIdx.x;
  const int c   = blockIdx.x;
  const int kh  = tid >> 4;          // 0..15  K-slice [kh*16, kh*16+16)
  const int jj  = (tid >> 2) & 3;    // local column
  const int bt  = tid & 3;           // batch octet [bt*8, bt*8+8)

  // ---- persistent weights in registers: wreg[g][i], k = kh*16+i ----
  float wreg[3][16];
#pragma unroll
  for (int g = 0; g < 3; ++g) {
    const float* wrow = w_hh + (size_t)(g * HH + c * 4 + jj) * HH + kh * 16;
#pragma unroll
    for (int i4 = 0; i4 < 4; ++i4) {
      float4 v = *(const float4*)(wrow + i4 * 4);
      wreg[g][i4 * 4 + 0] = v.x;
      wreg[g][i4 * 4 + 1] = v.y;
      wreg[g][i4 * 4 + 2] = v.z;
      wreg[g][i4 * 4 + 3] = v.w;
    }
  }
  if (tid < 12) bhh[tid] = b_hh[(tid >> 2) * HH + c * 4 + (tid & 3)];
  if (tid < 128) {  // initialize owned h columns (col-major)
    int b = tid >> 2, j2 = tid & 3;
    g_h[0][(c * 4 + j2) * BB + b] = hidden[b * HH + c * 4 + j2];
  }
  __syncthreads();
  if (tid == 0) {
    __threadfence();
    red_add(&g_ctr, 1u);
  }
  if (tid == 128) {  // wait for all CTAs' init
    while ((int)(ld_acq(&g_ctr) - 64u) < 0) {}
  }
  __syncthreads();

  float* myPart = part + tid * 25;

  for (int cell = 0; cell < NCELL; ++cell) {
    // ---- load h (col-major == hT layout) ----
    {
      const float4* src = (const float4*)(g_h[cell & 1]);
      float4* dst = (float4*)hT;
#pragma unroll
      for (int q = 0; q < 8; ++q)
        dst[tid + q * 256] = __ldcg(src + tid + q * 256);
    }
    // prefetch gi for epilogue threads (hidden behind compute)
    float gir = 0.f, giz = 0.f, gin = 0.f;
    if (tid < 128) {
      int b = tid >> 2, j2 = tid & 3;
      const float* gp = g_gi + (size_t)(cell >> 1) * BB * 768 + b * 768 + c * 4 + j2;
      gir = gp[0];
      giz = gp[256];
      gin = gp[512];
    }
    __syncthreads();

    // ---- partial gh with packed f32x2 FMA; weights from registers ----
    uint64_t acc[3][4];
#pragma unroll
    for (int g = 0; g < 3; ++g)
#pragma unroll
      for (int p = 0; p < 4; ++p) acc[g][p] = pack2(0.f, 0.f);

#pragma unroll
    for (int i = 0; i < 16; ++i) {
      const int k = kh * 16 + i;
      const float* hp = hT + k * 32 + bt * 8;
      const float4 ha = *(const float4*)hp;
      const float4 hb = *(const float4*)(hp + 4);
      const uint64_t h01 = pack2(ha.x, ha.y);
      const uint64_t h23 = pack2(ha.z, ha.w);
      const uint64_t h45 = pack2(hb.x, hb.y);
      const uint64_t h67 = pack2(hb.z, hb.w);
#pragma unroll
      for (int g = 0; g < 3; ++g) {
        const uint64_t w2 = pack2(wreg[g][i], wreg[g][i]);
        fma2(acc[g][0], w2, h01);
        fma2(acc[g][1], w2, h23);
        fma2(acc[g][2], w2, h45);
        fma2(acc[g][3], w2, h67);
      }
    }
    // store partials: per-thread contiguous block (stride 25 -> conflict-free)
#pragma unroll
    for (int g = 0; g < 3; ++g)
#pragma unroll
      for (int p = 0; p < 4; ++p) {
        float a, b;
        unpack2(a, b, acc[g][p]);
        myPart[(p * 2 + 0) * 3 + g] = a;
        myPart[(p * 2 + 1) * 3 + g] = b;
      }
    __syncthreads();

    // ---- epilogue (tids 0-127) overlapped with next-cell poll (tid 128) ----
    if (tid < 128) {
      const int b = tid >> 2, j2 = tid & 3;
      const int bt2 = b >> 3, bl = b & 7;
      float sr = bhh[j2], sz = bhh[4 + j2], sn = bhh[8 + j2];
#pragma unroll
      for (int k2 = 0; k2 < 16; ++k2) {
        const float* p = part + (k2 * 16 + j2 * 4 + bt2) * 25 + bl * 3;
        sr += p[0];
        sz += p[1];
        sn += p[2];
      }
      const float r = 1.f / (1.f + expf(-(gir + sr)));
      const float z = 1.f / (1.f + expf(-(giz + sz)));
      const float n = tanhf(gin + r * sn);
      const float hold = hT[(c * 4 + j2) * 32 + b];
      const float hn = (1.f - z) * n + z * hold;
      g_h[(cell + 1) & 1][(c * 4 + j2) * BB + b] = hn;
      if (cell & 1)
        out[((size_t)(cell >> 1) * BB + b) * HH + c * 4 + j2] = hn;
      asm volatile("bar.sync 1, 128;" ::: "memory");
      if (tid == 0) {
        __threadfence();
        red_add(&g_ctr, 1u);
      }
    } else if (tid == 128 && cell + 1 < NCELL) {
      const unsigned tgt = 64u * (unsigned)(cell + 2);
      while ((int)(ld_acq(&g_ctr) - tgt) < 0) {}
    }
    __syncthreads();
  }
}

// ---------------- launch --------------------------------------------------------
extern "C" void kernel_launch(void* const* d_in, const int* in_sizes, int n_in,
                              void* d_out, int out_size) {
  const float *input = 0, *hidden = 0, *w_ih = 0, *w_hh = 0, *b_ih = 0, *b_hh = 0;
  for (int i = 0; i < n_in; ++i) {
    long s = in_sizes[i];
    if (s == (long)BB * TT * HH) {
      input = (const float*)d_in[i];
    } else if (s == BB * HH && !hidden) {
      hidden = (const float*)d_in[i];
    } else if (s == 3 * HH * HH) {
      if (!w_ih) w_ih = (const float*)d_in[i]; else w_hh = (const float*)d_in[i];
    } else if (s == 3 * HH) {
      if (!b_ih) b_ih = (const float*)d_in[i]; else b_hh = (const float*)d_in[i];
    }
  }
  static int smem_set = 0;
  if (!smem_set) {
    cudaFuncSetAttribute(scan_kernel, cudaFuncAttributeMaxDynamicSharedMemorySize,
                         (HH * BB + 256 * 25 + 16) * (int)sizeof(float));
    smem_set = 1;
  }
  zero_ctr_kernel<<<1, 1>>>();
  gi_kernel<<<dim3(TT, 6), 256>>>(input, w_ih, b_ih);
  scan_kernel<<<NCTA, 256, (HH * BB + 256 * 25 + 16) * sizeof(float)>>>(
      hidden, w_hh, b_hh, (float*)d_out);
}